// round 7
// baseline (speedup 1.0000x reference)
#include <cuda_runtime.h>
#include <math.h>

#define B_ 4
#define T_ 8
#define C_ 128
#define HW_ 9216          // 96*96
#define NBT 32            // B*T
#define NCHUNK 72
#define CHUNK 16384
#define TILEP 32
#define NTILE 288         // HW_/TILEP
#define XP 132            // transposed row pitch (128 + 4 pad)

typedef unsigned long long ull;

__device__ __forceinline__ ull pack2(float a, float b) {
    ull r; asm("mov.b64 %0,{%1,%2};" : "=l"(r) : "f"(a), "f"(b)); return r;
}
__device__ __forceinline__ void unpack2(ull v, float& a, float& b) {
    asm("mov.b64 {%0,%1},%2;" : "=f"(a), "=f"(b) : "l"(v));
}
__device__ __forceinline__ ull fma2(ull a, ull b, ull c) {
    ull d; asm("fma.rn.f32x2 %0,%1,%2,%3;" : "=l"(d) : "l"(a), "l"(b), "l"(c)); return d;
}
__device__ __forceinline__ ull mul2(ull a, ull b) {
    ull d; asm("mul.rn.f32x2 %0,%1,%2;" : "=l"(d) : "l"(a), "l"(b)); return d;
}

// deterministic scratch
__device__ float g_psum[NBT * NCHUNK];
__device__ float g_psq [NBT * NCHUNK];
__device__ float g_A[NBT * C_];
__device__ float g_Bc[NBT * C_];
__device__ float g_WkT[C_ * C_];   // [c][h*32+d] = qkv_w[128 + h*32+d][c] * scale

// ---------------- Kernel 1: partial sums per (b,t) chunk ----------------
__global__ __launch_bounds__(256) void reduce_kernel(const float* __restrict__ x,
                                                     const float* __restrict__ pos) {
    int bt    = blockIdx.x / NCHUNK;
    int chunk = blockIdx.x % NCHUNK;
    int t     = bt & (T_ - 1);
    const float4* x4 = (const float4*)(x + (size_t)bt * C_ * HW_);
    int base4 = chunk * (CHUNK / 4);
    float s = 0.f, sq = 0.f;
#pragma unroll
    for (int i = 0; i < 16; i++) {
        int e4 = base4 + i * 256 + threadIdx.x;
        int c  = e4 / 2304;
        float pv = pos[t * C_ + c];
        float4 v = x4[e4];
        float a0 = v.x + pv, a1 = v.y + pv, a2 = v.z + pv, a3 = v.w + pv;
        s  += (a0 + a1) + (a2 + a3);
        sq += (a0 * a0 + a1 * a1) + (a2 * a2 + a3 * a3);
    }
    __shared__ float ss[8], ssq[8];
#pragma unroll
    for (int o = 16; o; o >>= 1) {
        s  += __shfl_down_sync(0xFFFFFFFFu, s, o);
        sq += __shfl_down_sync(0xFFFFFFFFu, sq, o);
    }
    int w = threadIdx.x >> 5;
    if ((threadIdx.x & 31) == 0) { ss[w] = s; ssq[w] = sq; }
    __syncthreads();
    if (threadIdx.x == 0) {
        float S = 0.f, SQ = 0.f;
#pragma unroll
        for (int i = 0; i < 8; i++) { S += ss[i]; SQ += ssq[i]; }
        g_psum[bt * NCHUNK + chunk] = S;
        g_psq [bt * NCHUNK + chunk] = SQ;
    }
}

// ---------------- Kernel 2: finalize mean/rstd -> affine A,B ----------------
__global__ __launch_bounds__(256) void finalize_kernel(const float* __restrict__ pos,
                                                       const float* __restrict__ nw,
                                                       const float* __restrict__ nb) {
    __shared__ float sm[NBT], sr[NBT];
    int tid = threadIdx.x;
    if (tid < NBT) {
        float S = 0.f, SQ = 0.f;
        for (int i = 0; i < NCHUNK; i++) { S += g_psum[tid * NCHUNK + i]; SQ += g_psq[tid * NCHUNK + i]; }
        const float invN = 1.0f / (float)(C_ * HW_);
        float mean = S * invN;
        float var  = SQ * invN - mean * mean;
        sm[tid] = mean;
        sr[tid] = rsqrtf(var + 1e-5f);
    }
    __syncthreads();
    for (int idx = tid; idx < NBT * C_; idx += 256) {
        int bt = idx >> 7, c = idx & 127, t = bt & (T_ - 1);
        float a = sr[bt] * nw[c];
        g_A[idx]  = a;
        g_Bc[idx] = (pos[t * C_ + c] - sm[bt]) * a + nb[c];
    }
}

// ---------------- Kernel 2b: transpose Wk (attention scale folded in) ----------------
__global__ __launch_bounds__(256) void wkT_kernel(const float* __restrict__ qkv_w) {
    int i = blockIdx.x * 256 + threadIdx.x;   // 0..16383
    int c = i >> 7, hd = i & 127;
    g_WkT[c * 128 + hd] = qkv_w[(128 + hd) * 128 + c] * 0.17677669529663687f;
}

// ---------------- Kernel 3: fused main ----------------
// smem float offsets
#define SM_XNT  0                      // 32*132 = 4224 (t=7 tile, transposed [p][c])
#define SM_QT   4224                   // 4224 (Q transposed [p][hd]; later OutT)
#define SM_U    8448                   // 16896: U [c][p] plain; later xbarT 4 heads x [p][132]
#define SM_P    25344                  // 2048 (logit partials, ping-pong)
#define SM_AB   27392                  // 2048 (A then B, [t*128+c])
#define SMEM_FLOATS 29440
#define SMEM_BYTES (SMEM_FLOATS * 4)   // 117760

// transposed-x GEMM core: 4 output rows x 4 pixels, pack over k-pairs.
// xT rows pitch XP; weights row-major pitch 128 (k contiguous). No packs needed.
__device__ __forceinline__ void gemmT(const float* __restrict__ wrow,
                                      const float* __restrict__ xT,
                                      int p0, int kdim, ull acc[4][4]) {
#pragma unroll
    for (int i = 0; i < 4; i++)
#pragma unroll
        for (int j = 0; j < 4; j++) acc[i][j] = 0ull;
#pragma unroll 4
    for (int k = 0; k < kdim; k += 4) {
        ulonglong2 xv[4];
#pragma unroll
        for (int j = 0; j < 4; j++)
            xv[j] = *(const ulonglong2*)(xT + (p0 + j) * XP + k);
#pragma unroll
        for (int i = 0; i < 4; i++) {
            ulonglong2 wv = *(const ulonglong2*)(wrow + i * C_ + k);
#pragma unroll
            for (int j = 0; j < 4; j++) {
                acc[i][j] = fma2(wv.x, xv[j].x, acc[i][j]);
                acc[i][j] = fma2(wv.y, xv[j].y, acc[i][j]);
            }
        }
    }
}
// reduce k-parity pairs to scalars
__device__ __forceinline__ void accres(ull acc[4][4], float res[4][4]) {
#pragma unroll
    for (int i = 0; i < 4; i++)
#pragma unroll
        for (int j = 0; j < 4; j++) {
            float lo, hi; unpack2(acc[i][j], lo, hi); res[i][j] = lo + hi;
        }
}

__global__ __launch_bounds__(256, 1) void main_kernel(const float* __restrict__ x,
                                                      const float* __restrict__ qkv_w,
                                                      const float* __restrict__ proj_w,
                                                      float* __restrict__ out) {
    extern __shared__ float sm[];
    float* sXNt = sm + SM_XNT;
    float* sQt  = sm + SM_QT;
    float* sU   = sm + SM_U;
    float* sAB  = sm + SM_AB;

    int b    = blockIdx.x / NTILE;
    int tile = blockIdx.x % NTILE;
    int hw0  = tile * TILEP;
    int tid  = threadIdx.x;
    int cg   = tid >> 3;   // GEMM: row group 0..31
    int pg   = tid & 7;    // GEMM: pixel group
    int p0   = pg * 4;
    int cld  = tid >> 5;   // attention: warp id 0..7 (c-set {cld+8j})
    int pld  = tid & 31;   // attention: pixel

    // ---- stage A/B affine tables for this b ----
    for (int idx = tid; idx < 1024; idx += 256) {
        sAB[idx]        = g_A [b * T_ * C_ + idx];
        sAB[1024 + idx] = g_Bc[b * T_ * C_ + idx];
    }

    // ---- Phase A: normalized tile at t=T-1, stored TRANSPOSED [p][c] ----
    {
        int bt = b * T_ + (T_ - 1);
        const float* xb = x + (size_t)bt * C_ * HW_;
        const float* Ab = g_A  + bt * C_;
        const float* Bb = g_Bc + bt * C_;
#pragma unroll
        for (int j = 0; j < 16; j++) {
            int c = cld + j * 8;
            sXNt[pld * XP + c] = xb[c * HW_ + hw0 + pld] * Ab[c] + Bb[c];
        }
    }
    __syncthreads();

    // prefetch t=0 raw x (overlaps Q and U GEMMs)
    float xr[16];
    {
        const float* xb = x + (size_t)(b * T_) * C_ * HW_;
#pragma unroll
        for (int jj = 0; jj < 8; jj++) {
            xr[2 * jj]     = xb[(cld + 16 * jj    ) * HW_ + hw0 + pld];
            xr[2 * jj + 1] = xb[(cld + 16 * jj + 8) * HW_ + hw0 + pld];
        }
    }

    // ---- Q GEMM -> sQt transposed [p][hd] ----
    {
        ull acc[4][4]; float res[4][4];
        gemmT(qkv_w + (size_t)(cg * 4) * C_, sXNt, p0, 128, acc);
        accres(acc, res);
#pragma unroll
        for (int j = 0; j < 4; j++) {
            float4 o; o.x = res[0][j]; o.y = res[1][j]; o.z = res[2][j]; o.w = res[3][j];
            *(float4*)(sQt + (p0 + j) * XP + cg * 4) = o;
        }
    }
    __syncthreads();

    // ---- U_h[c][p] = sum_d WkT[c][hd]*Q[hd][p] -> sU [c][p] plain ----
#pragma unroll
    for (int h = 0; h < 4; h++) {
        ull acc[4][4]; float res[4][4];
        gemmT(g_WkT + (size_t)(cg * 4) * C_ + h * 32, sQt + h * 32, p0, 32, acc);
        accres(acc, res);
#pragma unroll
        for (int i = 0; i < 4; i++) {
            float4 o; o.x = res[i][0]; o.y = res[i][1]; o.z = res[i][2]; o.w = res[i][3];
            *(float4*)(sU + (h * 128 + cg * 4 + i) * 32 + p0) = o;
        }
    }
    __syncthreads();

    // ---- load U into registers (attention layout), packed over c-pairs (c, c+8) ----
    ull uP[4][8];
#pragma unroll
    for (int h = 0; h < 4; h++)
#pragma unroll
        for (int jj = 0; jj < 8; jj++) {
            float a0 = sU[(h * 128 + cld + 16 * jj    ) * 32 + pld];
            float a1 = sU[(h * 128 + cld + 16 * jj + 8) * 32 + pld];
            uP[h][jj] = pack2(a0, a1);
        }

    // xn for t=7 from sXNt (transposed reads, one-time)
    ull xnP[8];
#pragma unroll
    for (int jj = 0; jj < 8; jj++) {
        float a0 = sXNt[pld * XP + cld + 16 * jj];
        float a1 = sXNt[pld * XP + cld + 16 * jj + 8];
        xnP[jj] = pack2(a0, a1);
    }
    __syncthreads();   // sU reads done before loop-end overwrite (xbarT)

    // register-resident online softmax + xbar accumulation
    ull   xbarP[4][8];
#pragma unroll
    for (int h = 0; h < 4; h++)
#pragma unroll
        for (int jj = 0; jj < 8; jj++) xbarP[h][jj] = 0ull;
    float m_run[4] = {-1e30f, -1e30f, -1e30f, -1e30f};
    float s_run[4] = {0.f, 0.f, 0.f, 0.f};

    for (int it = 0; it < T_; it++) {
        int s = (it == 0) ? (T_ - 1) : (it - 1);
        float* sPb = sm + SM_P + (it & 1) * 1024;   // ping-pong partial buffer
        if (it > 0) {
            // normalize xr -> xnP (registers only)
            const float* As = sAB + s * 128;
            const float* Bs = sAB + 1024 + s * 128;
#pragma unroll
            for (int jj = 0; jj < 8; jj++) {
                int c0 = cld + 16 * jj;
                float a0 = xr[2 * jj]     * As[c0]     + Bs[c0];
                float a1 = xr[2 * jj + 1] * As[c0 + 8] + Bs[c0 + 8];
                xnP[jj] = pack2(a0, a1);
            }
        }
        if (it >= 1 && it < T_ - 1) {   // prefetch raw x for t=it (used next iter)
            const float* xb = x + (size_t)(b * T_ + it) * C_ * HW_;
#pragma unroll
            for (int jj = 0; jj < 8; jj++) {
                xr[2 * jj]     = xb[(cld + 16 * jj    ) * HW_ + hw0 + pld];
                xr[2 * jj + 1] = xb[(cld + 16 * jj + 8) * HW_ + hw0 + pld];
            }
        }

        // logit partials over this thread's 16 c (pure register fma2)
        ull lg[4] = {0ull, 0ull, 0ull, 0ull};
#pragma unroll
        for (int jj = 0; jj < 8; jj++) {
            lg[0] = fma2(xnP[jj], uP[0][jj], lg[0]);
            lg[1] = fma2(xnP[jj], uP[1][jj], lg[1]);
            lg[2] = fma2(xnP[jj], uP[2][jj], lg[2]);
            lg[3] = fma2(xnP[jj], uP[3][jj], lg[3]);
        }
        float4 part;
        { float lo, hi;
          unpack2(lg[0], lo, hi); part.x = lo + hi;
          unpack2(lg[1], lo, hi); part.y = lo + hi;
          unpack2(lg[2], lo, hi); part.z = lo + hi;
          unpack2(lg[3], lo, hi); part.w = lo + hi; }
        *(float4*)(sPb + (cld * 32 + pld) * 4) = part;
        __syncthreads();

        // reduce 8 partials (redundant per pixel, deterministic); no trailing sync
        float L[4] = {0.f, 0.f, 0.f, 0.f};
#pragma unroll
        for (int k = 0; k < 8; k++) {
            float4 v = *(const float4*)(sPb + (k * 32 + pld) * 4);
            L[0] += v.x; L[1] += v.y; L[2] += v.z; L[3] += v.w;
        }

        // per-head softmax state + xbar update (registers only, fast exp)
#pragma unroll
        for (int h = 0; h < 4; h++) {
            float mn   = fmaxf(m_run[h], L[h]);
            float corr = __expf(m_run[h] - mn);
            float e    = __expf(L[h] - mn);
            s_run[h] = s_run[h] * corr + e;
            m_run[h] = mn;
            ull cP = pack2(corr, corr);
            ull eP = pack2(e, e);
#pragma unroll
            for (int jj = 0; jj < 8; jj++)
                xbarP[h][jj] = fma2(eP, xnP[jj], mul2(cP, xbarP[h][jj]));
        }
    }
    __syncthreads();

    // normalize xbar and write TRANSPOSED per head into sU region (U dead)
#pragma unroll
    for (int h = 0; h < 4; h++) {
        float inv = 1.0f / s_run[h];
        ull iP = pack2(inv, inv);
#pragma unroll
        for (int jj = 0; jj < 8; jj++) {
            float lo, hi;
            unpack2(mul2(iP, xbarP[h][jj]), lo, hi);
            sU[h * 4224 + pld * XP + cld + 16 * jj]     = lo;
            sU[h * 4224 + pld * XP + cld + 16 * jj + 8] = hi;
        }
    }
    __syncthreads();

    // ---- Phase E: Out[hd][p] = Wv . xbar_h -> sQt transposed [p][hd] ----
    {
        ull acc[4][4]; float res[4][4];
        gemmT(qkv_w + (size_t)(256 + cg * 4) * C_, sU + (cg >> 3) * 4224, p0, 128, acc);
        accres(acc, res);
#pragma unroll
        for (int j = 0; j < 4; j++) {
            float4 o; o.x = res[0][j]; o.y = res[1][j]; o.z = res[2][j]; o.w = res[3][j];
            *(float4*)(sQt + (p0 + j) * XP + cg * 4) = o;
        }
    }
    __syncthreads();

    // ---- Phase F: projection -> gmem ----
    {
        ull acc[4][4]; float res[4][4];
        gemmT(proj_w + (size_t)(cg * 4) * C_, sQt, p0, 128, acc);
        accres(acc, res);
#pragma unroll
        for (int i = 0; i < 4; i++) {
            float4 o; o.x = res[i][0]; o.y = res[i][1]; o.z = res[i][2]; o.w = res[i][3];
            *(float4*)(out + ((size_t)b * C_ + cg * 4 + i) * HW_ + hw0 + p0) = o;
        }
    }
}

extern "C" void kernel_launch(void* const* d_in, const int* in_sizes, int n_in,
                              void* d_out, int out_size) {
    const float* x    = (const float*)d_in[0];
    const float* pos  = (const float*)d_in[1];
    const float* nw   = (const float*)d_in[2];
    const float* nb   = (const float*)d_in[3];
    const float* qkvw = (const float*)d_in[4];
    const float* pw   = (const float*)d_in[5];
    float* out = (float*)d_out;

    reduce_kernel<<<NBT * NCHUNK, 256>>>(x, pos);
    finalize_kernel<<<1, 256>>>(pos, nw, nb);
    wkT_kernel<<<64, 256>>>(qkvw);
    cudaFuncSetAttribute(main_kernel, cudaFuncAttributeMaxDynamicSharedMemorySize, SMEM_BYTES);
    main_kernel<<<B_ * NTILE, 256, SMEM_BYTES>>>(x, qkvw, pw, out);
}

// round 9
// speedup vs baseline: 2.0287x; 2.0287x over previous
#include <cuda_runtime.h>
#include <cuda_bf16.h>
#include <math.h>
#include <cstdint>

#define B_ 4
#define T_ 8
#define C_ 128
#define HW_ 9216
#define NBT 32
#define NCHUNK 72
#define CHUNK 16384
#define TILEP 32
#define NTILE 288

typedef unsigned long long ull;
typedef unsigned int u32;

__device__ __forceinline__ ull pack2(float a, float b) {
    ull r; asm("mov.b64 %0,{%1,%2};" : "=l"(r) : "f"(a), "f"(b)); return r;
}
__device__ __forceinline__ void unpack2(ull v, float& a, float& b) {
    asm("mov.b64 {%0,%1},%2;" : "=f"(a), "=f"(b) : "l"(v));
}
__device__ __forceinline__ ull fma2(ull a, ull b, ull c) {
    ull d; asm("fma.rn.f32x2 %0,%1,%2,%3;" : "=l"(d) : "l"(a), "l"(b), "l"(c)); return d;
}
__device__ __forceinline__ ull mul2(ull a, ull b) {
    ull d; asm("mul.rn.f32x2 %0,%1,%2;" : "=l"(d) : "l"(a), "l"(b)); return d;
}

// hi/lo bf16 split of two floats -> two b32 (low half = first element)
__device__ __forceinline__ void split_store(float v0, float v1, u32* H, u32* L, int idx) {
    __nv_bfloat16 h0 = __float2bfloat16(v0);
    __nv_bfloat16 h1 = __float2bfloat16(v1);
    float r0 = v0 - __bfloat162float(h0);
    float r1 = v1 - __bfloat162float(h1);
    __nv_bfloat162 hh; hh.x = h0; hh.y = h1;
    __nv_bfloat162 llv; llv.x = __float2bfloat16(r0); llv.y = __float2bfloat16(r1);
    H[idx] = *(u32*)&hh;
    L[idx] = *(u32*)&llv;
}

// m16n8k16 row.col f32.bf16.bf16.f32
__device__ __forceinline__ void mma16816(float c[4], const u32 a[4], const u32 b[2]) {
    asm volatile("mma.sync.aligned.m16n8k16.row.col.f32.bf16.bf16.f32 "
                 "{%0,%1,%2,%3},{%4,%5,%6,%7},{%8,%9},{%0,%1,%2,%3};"
                 : "+f"(c[0]), "+f"(c[1]), "+f"(c[2]), "+f"(c[3])
                 : "r"(a[0]), "r"(a[1]), "r"(a[2]), "r"(a[3]), "r"(b[0]), "r"(b[1]));
}

// deterministic scratch
__device__ float g_psum[NBT * NCHUNK];
__device__ float g_psq [NBT * NCHUNK];
__device__ float g_A[NBT * C_];
__device__ float g_Bc[NBT * C_];
// 4 matrices x (hi plane 8192 + lo plane 8192) b32 bf16x2 pairs over k: [m][k/2]
__device__ u32 g_Wpk[4 * 16384];

// ---------------- Kernel 1: partial sums ----------------
__global__ __launch_bounds__(256) void reduce_kernel(const float* __restrict__ x,
                                                     const float* __restrict__ pos) {
    int bt = blockIdx.x / NCHUNK, chunk = blockIdx.x % NCHUNK, t = bt & (T_ - 1);
    const float4* x4 = (const float4*)(x + (size_t)bt * C_ * HW_);
    int base4 = chunk * (CHUNK / 4);
    float s = 0.f, sq = 0.f;
#pragma unroll
    for (int i = 0; i < 16; i++) {
        int e4 = base4 + i * 256 + threadIdx.x;
        int c = e4 / 2304;
        float pv = pos[t * C_ + c];
        float4 v = x4[e4];
        float a0 = v.x + pv, a1 = v.y + pv, a2 = v.z + pv, a3 = v.w + pv;
        s += (a0 + a1) + (a2 + a3);
        sq += (a0 * a0 + a1 * a1) + (a2 * a2 + a3 * a3);
    }
    __shared__ float ss[8], ssq[8];
#pragma unroll
    for (int o = 16; o; o >>= 1) {
        s += __shfl_down_sync(0xFFFFFFFFu, s, o);
        sq += __shfl_down_sync(0xFFFFFFFFu, sq, o);
    }
    int w = threadIdx.x >> 5;
    if ((threadIdx.x & 31) == 0) { ss[w] = s; ssq[w] = sq; }
    __syncthreads();
    if (threadIdx.x == 0) {
        float S = 0.f, SQ = 0.f;
#pragma unroll
        for (int i = 0; i < 8; i++) { S += ss[i]; SQ += ssq[i]; }
        g_psum[bt * NCHUNK + chunk] = S;
        g_psq [bt * NCHUNK + chunk] = SQ;
    }
}

// ---------------- Kernel 2: finalize ----------------
__global__ __launch_bounds__(256) void finalize_kernel(const float* __restrict__ pos,
                                                       const float* __restrict__ nw,
                                                       const float* __restrict__ nb) {
    __shared__ float sm[NBT], sr[NBT];
    int tid = threadIdx.x;
    if (tid < NBT) {
        float S = 0.f, SQ = 0.f;
        for (int i = 0; i < NCHUNK; i++) { S += g_psum[tid * NCHUNK + i]; SQ += g_psq[tid * NCHUNK + i]; }
        const float invN = 1.0f / (float)(C_ * HW_);
        float mean = S * invN;
        float var = SQ * invN - mean * mean;
        sm[tid] = mean;
        sr[tid] = rsqrtf(var + 1e-5f);
    }
    __syncthreads();
    for (int idx = tid; idx < NBT * C_; idx += 256) {
        int bt = idx >> 7, c = idx & 127, t = bt & (T_ - 1);
        float a = sr[bt] * nw[c];
        g_A[idx] = a;
        g_Bc[idx] = (pos[t * C_ + c] - sm[bt]) * a + nb[c];
    }
}

// ---------------- Kernel 2b: weight prep (hi/lo split, bf16x2 pairs over k) ----------------
__global__ __launch_bounds__(256) void wprep_kernel(const float* __restrict__ qkv_w,
                                                    const float* __restrict__ proj_w) {
    int i = blockIdx.x * 256 + threadIdx.x;   // 0..32767
    int mat = i >> 13, idx = i & 8191, r = idx >> 6, c2 = idx & 63;
    int c = 2 * c2;
    float w0, w1;
    const float sc = 0.17677669529663687f;
    if (mat == 0)      { w0 = qkv_w[r * 128 + c];             w1 = qkv_w[r * 128 + c + 1]; }
    else if (mat == 1) { w0 = qkv_w[(128 + c) * 128 + r] * sc; w1 = qkv_w[(128 + c + 1) * 128 + r] * sc; }
    else if (mat == 2) { w0 = qkv_w[(256 + r) * 128 + c];     w1 = qkv_w[(256 + r) * 128 + c + 1]; }
    else               { w0 = proj_w[r * 128 + c];            w1 = proj_w[r * 128 + c + 1]; }
    split_store(w0, w1, g_Wpk + mat * 16384, g_Wpk + mat * 16384 + 8192, r * 64 + c2);
}

// ---------------- Kernel 3: fused main with mma.sync GEMMs ----------------
// smem offsets in floats/b32 units
#define PB 40               // B-tile pitch (b32): 40 % 32 == 8 -> conflict-free fragments
#define PD 33               // f32 scratch pitch
#define SM_B0H 0            // 2560
#define SM_B0L 2560         // 2560
#define SM_BIG 5120         // 20480: U f32 scratch [h][c][px] pitch 33; then E B-tiles (h: hi@h*5120, lo@+2560)
#define SM_D   25600        // 4224 f32 scratch pitch 33
#define SM_AB  29824        // 2048
#define SM_P   31872        // 1024
#define SMEM_FLOATS 32896
#define SMEM_BYTES (SMEM_FLOATS * 4)   // 131584

// one compensated GEMM slice: warp rows [m0,m0+16), all 32 px, ks in [ks0, ks0+ksn)
__device__ __forceinline__ void gemm_mma(const u32* __restrict__ Whi, const u32* __restrict__ Wlo,
                                         const u32* Bh, const u32* Bl,
                                         int m0, int g, int t, int ks0, int ksn, float acc[4][4]) {
#pragma unroll
    for (int ki = 0; ki < ksn; ki++) {
        int ks = ks0 + ki;
        int rA = (m0 + g) * 64 + 8 * ks + t;
        int rA8 = rA + 8 * 64;
        u32 aH[4] = {Whi[rA], Whi[rA8], Whi[rA + 4], Whi[rA8 + 4]};
        u32 aL[4] = {Wlo[rA], Wlo[rA8], Wlo[rA + 4], Wlo[rA8 + 4]};
        int rB0 = (8 * ks + t) * PB + g;
        int rB1 = rB0 + 4 * PB;
#pragma unroll
        for (int nt = 0; nt < 4; nt++) {
            u32 bh[2] = {Bh[rB0 + 8 * nt], Bh[rB1 + 8 * nt]};
            u32 bl[2] = {Bl[rB0 + 8 * nt], Bl[rB1 + 8 * nt]};
            mma16816(acc[nt], aH, bh);
            mma16816(acc[nt], aL, bh);
            mma16816(acc[nt], aH, bl);
        }
    }
}

__global__ __launch_bounds__(256, 1) void main_kernel(const float* __restrict__ x,
                                                      float* __restrict__ out) {
    extern __shared__ float sm[];
    u32* sB0H = (u32*)(sm + SM_B0H);
    u32* sB0L = (u32*)(sm + SM_B0L);
    float* sBIG = sm + SM_BIG;
    float* sD  = sm + SM_D;
    float* sAB = sm + SM_AB;
    float* sP  = sm + SM_P;

    int b    = blockIdx.x / NTILE;
    int tile = blockIdx.x % NTILE;
    int hw0  = tile * TILEP;
    int tid  = threadIdx.x;
    int wid  = tid >> 5, lane = tid & 31;
    int g    = lane >> 2, t = lane & 3;
    int m0   = 16 * wid;
    int cld  = wid;          // attention: contiguous c-block [16*cld, 16*cld+16)
    int pld  = lane;
    int c0   = cld * 16;

    // stage affine tables
    for (int idx = tid; idx < 1024; idx += 256) {
        sAB[idx]        = g_A [b * 1024 + idx];
        sAB[1024 + idx] = g_Bc[b * 1024 + idx];
    }
    // raw x7 + t0 prefetch
    float xn[16], xr[16];
    {
        const float* xb7 = x + (size_t)(b * T_ + 7) * C_ * HW_;
        const float* xb0 = x + (size_t)(b * T_) * C_ * HW_;
#pragma unroll
        for (int j = 0; j < 16; j++) xn[j] = xb7[(c0 + j) * HW_ + hw0 + pld];
#pragma unroll
        for (int j = 0; j < 16; j++) xr[j] = xb0[(c0 + j) * HW_ + hw0 + pld];
    }
    __syncthreads();

    // normalize x7 in regs; pack B tile (slot0)
    {
        const float* As = sAB + 7 * 128;
        const float* Bs = sAB + 1024 + 7 * 128;
#pragma unroll
        for (int j = 0; j < 16; j++) xn[j] = xn[j] * As[c0 + j] + Bs[c0 + j];
#pragma unroll
        for (int k = 0; k < 8; k++)
            split_store(xn[2 * k], xn[2 * k + 1], sB0H, sB0L, (8 * cld + k) * PB + pld);
    }
    __syncthreads();

    // ---- Phase Q: Q[m][px] = Wq @ XN7 ----
    {
        float acc[4][4] = {};
        gemm_mma(g_Wpk, g_Wpk + 8192, sB0H, sB0L, m0, g, t, 0, 8, acc);
#pragma unroll
        for (int nt = 0; nt < 4; nt++) {
            int base  = (m0 + g) * PD + 8 * nt + 2 * t;
            int base8 = base + 8 * PD;
            sD[base] = acc[nt][0]; sD[base + 1] = acc[nt][1];
            sD[base8] = acc[nt][2]; sD[base8 + 1] = acc[nt][3];
        }
    }
    __syncthreads();
    // repack Q (f32 scratch) -> slot0 hi/lo
#pragma unroll
    for (int j = 0; j < 8; j++) {
        int k2 = (tid >> 5) + 8 * j, px = tid & 31;
        split_store(sD[(2 * k2) * PD + px], sD[(2 * k2 + 1) * PD + px], sB0H, sB0L, k2 * PB + px);
    }
    __syncthreads();

    // ---- Phase U: per head h, U_h[c][px] = WkT[:, 32h..] @ Q_h  (K=32 => ks {2h,2h+1}) ----
    {
        const u32* Whi = g_Wpk + 16384;
        const u32* Wlo = g_Wpk + 16384 + 8192;
#pragma unroll
        for (int h = 0; h < 4; h++) {
            float acc[4][4] = {};
            gemm_mma(Whi, Wlo, sB0H, sB0L, m0, g, t, 2 * h, 2, acc);
            float* uD = sBIG + h * 4224;
#pragma unroll
            for (int nt = 0; nt < 4; nt++) {
                int base  = (m0 + g) * PD + 8 * nt + 2 * t;
                int base8 = base + 8 * PD;
                uD[base] = acc[nt][0]; uD[base + 1] = acc[nt][1];
                uD[base8] = acc[nt][2]; uD[base8 + 1] = acc[nt][3];
            }
        }
    }
    __syncthreads();

    // load U into regs (adjacent c-pairs)
    ull uP[4][8];
#pragma unroll
    for (int h = 0; h < 4; h++)
#pragma unroll
        for (int k = 0; k < 8; k++)
            uP[h][k] = pack2(sBIG[h * 4224 + (c0 + 2 * k) * PD + pld],
                             sBIG[h * 4224 + (c0 + 2 * k + 1) * PD + pld]);

    ull xnP[8];
#pragma unroll
    for (int k = 0; k < 8; k++) xnP[k] = pack2(xn[2 * k], xn[2 * k + 1]);

    // ---- register-resident online softmax + xbar (r4-proven) ----
    ull xbarP[4][8];
#pragma unroll
    for (int h = 0; h < 4; h++)
#pragma unroll
        for (int k = 0; k < 8; k++) xbarP[h][k] = 0ull;
    float m_run[4] = {-1e30f, -1e30f, -1e30f, -1e30f};
    float s_run[4] = {0.f, 0.f, 0.f, 0.f};

    for (int it = 0; it < T_; it++) {
        int s = (it == 0) ? (T_ - 1) : (it - 1);
        if (it > 0) {
            const float* As = sAB + s * 128;
            const float* Bs = sAB + 1024 + s * 128;
#pragma unroll
            for (int k = 0; k < 8; k++) {
                float a0 = xr[2 * k] * As[c0 + 2 * k] + Bs[c0 + 2 * k];
                float a1 = xr[2 * k + 1] * As[c0 + 2 * k + 1] + Bs[c0 + 2 * k + 1];
                xnP[k] = pack2(a0, a1);
            }
        }
        if (it >= 1 && it < T_ - 1) {
            const float* xb = x + (size_t)(b * T_ + it) * C_ * HW_;
#pragma unroll
            for (int j = 0; j < 16; j++) xr[j] = xb[(c0 + j) * HW_ + hw0 + pld];
        }
        ull lg[4] = {0ull, 0ull, 0ull, 0ull};
#pragma unroll
        for (int k = 0; k < 8; k++) {
            lg[0] = fma2(xnP[k], uP[0][k], lg[0]);
            lg[1] = fma2(xnP[k], uP[1][k], lg[1]);
            lg[2] = fma2(xnP[k], uP[2][k], lg[2]);
            lg[3] = fma2(xnP[k], uP[3][k], lg[3]);
        }
        float4 part;
        { float lo, hi;
          unpack2(lg[0], lo, hi); part.x = lo + hi;
          unpack2(lg[1], lo, hi); part.y = lo + hi;
          unpack2(lg[2], lo, hi); part.z = lo + hi;
          unpack2(lg[3], lo, hi); part.w = lo + hi; }
        *(float4*)(sP + (cld * 32 + pld) * 4) = part;
        __syncthreads();
        float L[4] = {0.f, 0.f, 0.f, 0.f};
#pragma unroll
        for (int k = 0; k < 8; k++) {
            float4 v = *(const float4*)(sP + (k * 32 + pld) * 4);
            L[0] += v.x; L[1] += v.y; L[2] += v.z; L[3] += v.w;
        }
        __syncthreads();
#pragma unroll
        for (int h = 0; h < 4; h++) {
            float mn = fmaxf(m_run[h], L[h]);
            float corr = __expf(m_run[h] - mn);
            float e = __expf(L[h] - mn);
            s_run[h] = s_run[h] * corr + e;
            m_run[h] = mn;
            ull cP = pack2(corr, corr), eP = pack2(e, e);
#pragma unroll
            for (int k = 0; k < 8; k++)
                xbarP[h][k] = fma2(eP, xnP[k], mul2(cP, xbarP[h][k]));
        }
    }
    __syncthreads();   // uP/sBIG reads done; sBIG becomes E B-tiles

    // normalize xbar -> E B-tiles (per head hi/lo planes)
#pragma unroll
    for (int h = 0; h < 4; h++) {
        float inv = 1.0f / s_run[h];
        ull iP = pack2(inv, inv);
        u32* EH = (u32*)(sBIG + h * 5120);
        u32* EL = (u32*)(sBIG + h * 5120 + 2560);
#pragma unroll
        for (int k = 0; k < 8; k++) {
            float v0, v1;
            unpack2(mul2(iP, xbarP[h][k]), v0, v1);
            split_store(v0, v1, EH, EL, (8 * cld + k) * PB + pld);
        }
    }
    __syncthreads();

    // ---- Phase E: warp w -> head h=w>>1; Out[hd][px] = Wv @ xbar_h (rows m0..m0+16) ----
    {
        int h = wid >> 1;
        const u32* Whi = g_Wpk + 2 * 16384;
        const u32* Wlo = g_Wpk + 2 * 16384 + 8192;
        u32* EH = (u32*)(sBIG + h * 5120);
        u32* EL = (u32*)(sBIG + h * 5120 + 2560);
        float acc[4][4] = {};
        gemm_mma(Whi, Wlo, EH, EL, m0, g, t, 0, 8, acc);
#pragma unroll
        for (int nt = 0; nt < 4; nt++) {
            int base  = (m0 + g) * PD + 8 * nt + 2 * t;
            int base8 = base + 8 * PD;
            sD[base] = acc[nt][0]; sD[base + 1] = acc[nt][1];
            sD[base8] = acc[nt][2]; sD[base8 + 1] = acc[nt][3];
        }
    }
    __syncthreads();
    // repack Out -> slot0
#pragma unroll
    for (int j = 0; j < 8; j++) {
        int k2 = (tid >> 5) + 8 * j, px = tid & 31;
        split_store(sD[(2 * k2) * PD + px], sD[(2 * k2 + 1) * PD + px], sB0H, sB0L, k2 * PB + px);
    }
    __syncthreads();

    // ---- Phase F: y = proj @ Out -> gmem direct ----
    {
        const u32* Whi = g_Wpk + 3 * 16384;
        const u32* Wlo = g_Wpk + 3 * 16384 + 8192;
        float acc[4][4] = {};
        gemm_mma(Whi, Wlo, sB0H, sB0L, m0, g, t, 0, 8, acc);
        float* o0 = out + ((size_t)b * C_ + m0 + g) * HW_ + hw0;
        float* o8 = out + ((size_t)b * C_ + m0 + g + 8) * HW_ + hw0;
#pragma unroll
        for (int nt = 0; nt < 4; nt++) {
            int px = 8 * nt + 2 * t;
            *(float2*)(o0 + px) = make_float2(acc[nt][0], acc[nt][1]);
            *(float2*)(o8 + px) = make_float2(acc[nt][2], acc[nt][3]);
        }
    }
}

extern "C" void kernel_launch(void* const* d_in, const int* in_sizes, int n_in,
                              void* d_out, int out_size) {
    const float* x    = (const float*)d_in[0];
    const float* pos  = (const float*)d_in[1];
    const float* nw   = (const float*)d_in[2];
    const float* nb   = (const float*)d_in[3];
    const float* qkvw = (const float*)d_in[4];
    const float* pw   = (const float*)d_in[5];
    float* out = (float*)d_out;

    reduce_kernel<<<NBT * NCHUNK, 256>>>(x, pos);
    finalize_kernel<<<1, 256>>>(pos, nw, nb);
    wprep_kernel<<<128, 256>>>(qkvw, pw);
    cudaFuncSetAttribute(main_kernel, cudaFuncAttributeMaxDynamicSharedMemorySize, SMEM_BYTES);
    main_kernel<<<B_ * NTILE, 256, SMEM_BYTES>>>(x, out);
}